// round 3
// baseline (speedup 1.0000x reference)
#include <cuda_runtime.h>
#include <cuda_bf16.h>
#include <math.h>
#include <stdint.h>

// RobustCombiner: B=4,S=512,K=32,MID=32,V=32000
// One block per (b,s) row. Phase 1: stream network_probs row (top-8 scan) while
// zeroing the output row. Phase 2: block-reduce exact sorted top-8.
// Phase 3 (warp 0): label counts, tiny MLPs, softmax, scatter, lambda.

#define KNN_K 32
#define NTHREADS 256

__device__ __forceinline__ float warpSumAll(float v) {
    #pragma unroll
    for (int o = 16; o > 0; o >>= 1) v += __shfl_xor_sync(0xffffffffu, v, o);
    return v;
}
__device__ __forceinline__ float warpMaxAll(float v) {
    #pragma unroll
    for (int o = 16; o > 0; o >>= 1) v = fmaxf(v, __shfl_xor_sync(0xffffffffu, v, o));
    return v;
}

__global__ __launch_bounds__(NTHREADS, 4)
void robust_combiner_kernel(
    const int*   __restrict__ tgt_index,       // [R,32]
    const float* __restrict__ knn_dists,       // [R,32]
    const float* __restrict__ knn_key_feature, // [R,32]
    const float* __restrict__ network_probs,   // [R,V]
    const float* __restrict__ net_sel_probs,   // [R,32]
    const float* __restrict__ W_func,  // [1,72]
    const float* __restrict__ b_func,  // [1]
    const float* __restrict__ W1a,     // [4,2]
    const float* __restrict__ b1a,     // [4]
    const float* __restrict__ W1b,     // [1,4]
    const float* __restrict__ b1b,     // [1]
    const float* __restrict__ W2a,     // [32,64]
    const float* __restrict__ b2a,     // [32]
    const float* __restrict__ W2b,     // [2,32]
    const float* __restrict__ b2b,     // [2]
    float* __restrict__ out,           // [R,V] then [R] lambda
    int V, int n_rows, int write_lambda)
{
    const int row = blockIdx.x;
    const int tid = threadIdx.x;

    __shared__ float cand[NTHREADS * 8];
    __shared__ float rv[NTHREADS];
    __shared__ int   ri[NTHREADS];
    __shared__ float s_top8[8];
    __shared__ float s_dist[KNN_K];
    __shared__ float s_cnt[KNN_K];

    // ---------------- Phase 1: stream row, keep per-thread top-8, zero output row
    float t0 = -INFINITY, t1 = -INFINITY, t2 = -INFINITY, t3 = -INFINITY;
    float t4 = -INFINITY, t5 = -INFINITY, t6 = -INFINITY, t7 = -INFINITY;

    const size_t rbase = (size_t)row * (size_t)V;
    const int nvec = V >> 2;                  // V=32000 -> 8000 float4
    const float4* src = reinterpret_cast<const float4*>(network_probs + rbase);
    float4*       dst = reinterpret_cast<float4*>(out + rbase);
    const float4 z4 = make_float4(0.f, 0.f, 0.f, 0.f);

    #define TOP8_INSERT(v)                                              \
        if ((v) > t7) {                                                 \
            t7 = (v);                                                   \
            float _tmp;                                                 \
            if (t7 > t6) { _tmp = t6; t6 = t7; t7 = _tmp; }             \
            if (t6 > t5) { _tmp = t5; t5 = t6; t6 = _tmp; }             \
            if (t5 > t4) { _tmp = t4; t4 = t5; t5 = _tmp; }             \
            if (t4 > t3) { _tmp = t3; t3 = t4; t4 = _tmp; }             \
            if (t3 > t2) { _tmp = t2; t2 = t3; t3 = _tmp; }             \
            if (t2 > t1) { _tmp = t1; t1 = t2; t2 = _tmp; }             \
            if (t1 > t0) { _tmp = t0; t0 = t1; t1 = _tmp; }             \
        }

    #pragma unroll 2
    for (int i = tid; i < nvec; i += NTHREADS) {
        float4 v = src[i];
        dst[i] = z4;
        TOP8_INSERT(v.x); TOP8_INSERT(v.y); TOP8_INSERT(v.z); TOP8_INSERT(v.w);
    }
    // scalar tail (V not divisible by 4)
    for (int i = (nvec << 2) + tid; i < V; i += NTHREADS) {
        float v = network_probs[rbase + i];
        out[rbase + i] = 0.f;
        TOP8_INSERT(v);
    }
    #undef TOP8_INSERT

    cand[tid * 8 + 0] = t0; cand[tid * 8 + 1] = t1;
    cand[tid * 8 + 2] = t2; cand[tid * 8 + 3] = t3;
    cand[tid * 8 + 4] = t4; cand[tid * 8 + 5] = t5;
    cand[tid * 8 + 6] = t6; cand[tid * 8 + 7] = t7;
    __syncthreads();

    // ---------------- Phase 2: 8 rounds of block argmax -> sorted descending top-8
    #pragma unroll 1
    for (int r = 0; r < 8; ++r) {
        float best = -INFINITY; int bi = tid * 8;
        #pragma unroll
        for (int j = 0; j < 8; ++j) {
            float c = cand[tid * 8 + j];
            if (c > best) { best = c; bi = tid * 8 + j; }
        }
        rv[tid] = best; ri[tid] = bi;
        __syncthreads();
        #pragma unroll
        for (int s = NTHREADS / 2; s > 0; s >>= 1) {
            if (tid < s) {
                if (rv[tid + s] > rv[tid]) { rv[tid] = rv[tid + s]; ri[tid] = ri[tid + s]; }
            }
            __syncthreads();
        }
        if (tid == 0) { s_top8[r] = rv[0]; cand[ri[0]] = -INFINITY; }
        __syncthreads();
    }

    // ---------------- Phase 3: per-row math (warp 0)
    if (tid < 32) {
        const int lane = tid;
        const size_t kb = (size_t)row * KNN_K + lane;
        const int   tgt  = tgt_index[kb];
        const float dist = knn_dists[kb];
        const float lkey = logf(knn_key_feature[kb]);
        const float lsel = logf(net_sel_probs[kb]);

        // duplicate-label group mask (used for counts AND scatter last-wins)
        unsigned mm = __match_any_sync(0xffffffffu, tgt);
        int first = __ffs(mm) - 1;
        int last  = 31 - __clz(mm);

        // distinct-label prefix counts (reference semantics: label 0 never counted)
        int cnt = (tgt != 0 && first == lane) ? 1 : 0;
        #pragma unroll
        for (int o = 1; o < 32; o <<= 1) {
            int n = __shfl_up_sync(0xffffffffu, cnt, o);
            if (lane >= o) cnt += n;
        }
        const float cntf = (float)cnt;

        // noise_logit: 2 -> 4 tanh -> 1
        float noise = b1b[0];
        #pragma unroll
        for (int a = 0; a < 4; ++a) {
            float h = tanhf(b1a[a] + W1a[a * 2] * lkey + W1a[a * 2 + 1] * lsel);
            noise += W1b[a] * h;
        }

        // sim_lambda = W_func . [log(top8), log_key, log_sel] + b_func
        float part = W_func[8 + lane] * lkey + W_func[40 + lane] * lsel;
        if (lane < 8) part += W_func[lane] * logf(s_top8[lane]);
        const float sim = warpSumAll(part) + b_func[0];

        // lambda_logit = W2b . tanh(W2a . [dists, counts] + b2a) + b2b
        s_dist[lane] = dist; s_cnt[lane] = cntf;
        __syncwarp();
        float h = b2a[lane];
        const float* w = W2a + lane * 64;
        #pragma unroll 8
        for (int k = 0; k < KNN_K; ++k)
            h += w[k] * s_dist[k] + w[KNN_K + k] * s_cnt[k];
        h = tanhf(h);
        const float l0 = warpSumAll(W2b[lane] * h) + b2b[0];
        const float l1 = warpSumAll(W2b[32 + lane] * h) + b2b[1];

        const float lam   = 1.f / (1.f + expf(sim - l0));  // softmax([l0,sim])[0]
        const float tempe = 1.f / (1.f + expf(-l1));

        // probs = softmax(-dist*tempe + noise) over K
        const float logit = -dist * tempe + noise;
        const float mx = warpMaxAll(logit);
        const float e  = expf(logit - mx);
        const float sm = warpSumAll(e);

        // scatter: for duplicate tgt within the row, LAST occurrence wins
        // (matches sequential XLA scatter order); row was zeroed in phase 1.
        if (lane == last)
            out[rbase + (size_t)tgt] = e / sm;
        if (lane == 0 && write_lambda)
            out[(size_t)n_rows * (size_t)V + row] = lam;
    }
}

extern "C" void kernel_launch(void* const* d_in, const int* in_sizes, int n_in,
                              void* d_out, int out_size)
{
    const int* tgt_index        = (const int*)  d_in[0];
    const float* knn_dists      = (const float*)d_in[1];
    const float* knn_key        = (const float*)d_in[2];
    const float* network_probs  = (const float*)d_in[3];
    const float* net_sel        = (const float*)d_in[4];
    const float* W_func = (const float*)d_in[5];
    const float* b_func = (const float*)d_in[6];
    const float* W1a    = (const float*)d_in[7];
    const float* b1a    = (const float*)d_in[8];
    const float* W1b    = (const float*)d_in[9];
    const float* b1b    = (const float*)d_in[10];
    const float* W2a    = (const float*)d_in[11];
    const float* b2a    = (const float*)d_in[12];
    const float* W2b    = (const float*)d_in[13];
    const float* b2b    = (const float*)d_in[14];

    const int n_rows = in_sizes[1] / KNN_K;            // B*S = 2048
    const int V      = in_sizes[3] / n_rows;           // 32000
    const int write_lambda =
        ((long long)out_size >= (long long)n_rows * V + n_rows) ? 1 : 0;

    robust_combiner_kernel<<<n_rows, NTHREADS>>>(
        tgt_index, knn_dists, knn_key, network_probs, net_sel,
        W_func, b_func, W1a, b1a, W1b, b1b, W2a, b2a, W2b, b2b,
        (float*)d_out, V, n_rows, write_lambda);
}

// round 5
// speedup vs baseline: 1.2392x; 1.2392x over previous
#include <cuda_runtime.h>
#include <cuda_bf16.h>
#include <math.h>
#include <stdint.h>

// RobustCombiner: B=4,S=512,K=32,MID=32,V=32000
// One block per (b,s) row.
// Phase 1: stream network_probs row with 4x-batched float4 loads; cheap max4
//          gate before the (rare) top-8 insert chain; zero output row in-pass.
// Phase 2: shuffle-only top-8 merge (per-warp head extraction, then warp 0
//          merges 8 sorted lists). One __syncthreads total.
// Phase 3 (warp 0): label counts, tiny MLPs, softmax, last-wins scatter, lambda.

#define KNN_K 32
#define NTHREADS 256
#define NWARPS (NTHREADS / 32)

__device__ __forceinline__ float warpSumAll(float v) {
    #pragma unroll
    for (int o = 16; o > 0; o >>= 1) v += __shfl_xor_sync(0xffffffffu, v, o);
    return v;
}
__device__ __forceinline__ float warpMaxAll(float v) {
    #pragma unroll
    for (int o = 16; o > 0; o >>= 1) v = fmaxf(v, __shfl_xor_sync(0xffffffffu, v, o));
    return v;
}

__global__ __launch_bounds__(NTHREADS, 4)
void robust_combiner_kernel(
    const int*   __restrict__ tgt_index,       // [R,32]
    const float* __restrict__ knn_dists,       // [R,32]
    const float* __restrict__ knn_key_feature, // [R,32]
    const float* __restrict__ network_probs,   // [R,V]
    const float* __restrict__ net_sel_probs,   // [R,32]
    const float* __restrict__ W_func,  // [1,72]
    const float* __restrict__ b_func,  // [1]
    const float* __restrict__ W1a,     // [4,2]
    const float* __restrict__ b1a,     // [4]
    const float* __restrict__ W1b,     // [1,4]
    const float* __restrict__ b1b,     // [1]
    const float* __restrict__ W2a,     // [32,64]
    const float* __restrict__ b2a,     // [32]
    const float* __restrict__ W2b,     // [2,32]
    const float* __restrict__ b2b,     // [2]
    float* __restrict__ out,           // [R,V] then [R] lambda
    int V, int n_rows, int write_lambda)
{
    const int row  = blockIdx.x;
    const int tid  = threadIdx.x;
    const int lane = tid & 31;
    const int wid  = tid >> 5;

    __shared__ float s_warp8[NWARPS][8];
    __shared__ float s_dist[KNN_K];
    __shared__ float s_cnt[KNN_K];

    // ---------------- Phase 1: stream row (4x batched), zero output row
    float t0 = -INFINITY, t1 = -INFINITY, t2 = -INFINITY, t3 = -INFINITY;
    float t4 = -INFINITY, t5 = -INFINITY, t6 = -INFINITY, t7 = -INFINITY;

    const size_t rbase = (size_t)row * (size_t)V;
    const int nvec = V >> 2;                  // 32000 -> 8000 float4
    const float4* src = reinterpret_cast<const float4*>(network_probs + rbase);
    float4*       dst = reinterpret_cast<float4*>(out + rbase);
    const float4 z4 = make_float4(0.f, 0.f, 0.f, 0.f);

    #define INS(v)                                                      \
        if ((v) > t7) {                                                 \
            t7 = (v);                                                   \
            float _tmp;                                                 \
            if (t7 > t6) { _tmp = t6; t6 = t7; t7 = _tmp; }             \
            if (t6 > t5) { _tmp = t5; t5 = t6; t6 = _tmp; }             \
            if (t5 > t4) { _tmp = t4; t4 = t5; t5 = _tmp; }             \
            if (t4 > t3) { _tmp = t3; t3 = t4; t4 = _tmp; }             \
            if (t3 > t2) { _tmp = t2; t2 = t3; t3 = _tmp; }             \
            if (t2 > t1) { _tmp = t1; t1 = t2; t2 = _tmp; }             \
            if (t1 > t0) { _tmp = t0; t0 = t1; t1 = _tmp; }             \
        }
    #define PROC4(v)                                                    \
        {                                                               \
            float _m = fmaxf(fmaxf((v).x, (v).y), fmaxf((v).z, (v).w)); \
            if (_m > t7) { INS((v).x); INS((v).y); INS((v).z); INS((v).w); } \
        }

    int i = tid;
    for (; i + 3 * NTHREADS < nvec; i += 4 * NTHREADS) {
        float4 a = __ldcs(&src[i]);
        float4 b = __ldcs(&src[i +     NTHREADS]);
        float4 c = __ldcs(&src[i + 2 * NTHREADS]);
        float4 d = __ldcs(&src[i + 3 * NTHREADS]);
        __stcs(&dst[i],                z4);
        __stcs(&dst[i +     NTHREADS], z4);
        __stcs(&dst[i + 2 * NTHREADS], z4);
        __stcs(&dst[i + 3 * NTHREADS], z4);
        PROC4(a); PROC4(b); PROC4(c); PROC4(d);
    }
    for (; i < nvec; i += NTHREADS) {
        float4 a = __ldcs(&src[i]);
        __stcs(&dst[i], z4);
        PROC4(a);
    }
    #undef PROC4
    #undef INS

    // Prefetch warp-0 phase-3 scalars (overlap with phase 2a)
    int   p_tgt = 0;
    float p_dist = 0.f, p_key = 1.f, p_sel = 1.f;
    if (wid == 0) {
        const size_t kb = (size_t)row * KNN_K + lane;
        p_tgt  = tgt_index[kb];
        p_dist = knn_dists[kb];
        p_key  = knn_key_feature[kb];
        p_sel  = net_sel_probs[kb];
    }

    // ---------------- Phase 2a: per-warp sorted top-8 via head extraction
    #pragma unroll
    for (int r = 0; r < 8; ++r) {
        float head = t0;
        float m = warpMaxAll(head);
        unsigned win = __ballot_sync(0xffffffffu, head == m);
        if (lane == __ffs(win) - 1) {
            t0 = t1; t1 = t2; t2 = t3; t3 = t4;
            t4 = t5; t5 = t6; t6 = t7; t7 = -INFINITY;
        }
        if (lane == 0) s_warp8[wid][r] = m;
    }
    __syncthreads();

    // ---------------- Phase 2b + Phase 3: warp 0 only
    if (wid == 0) {
        // merge 8 sorted lists (lanes 0-7 own one list each)
        float r0 = -INFINITY, r1 = -INFINITY, r2 = -INFINITY, r3 = -INFINITY;
        float r4 = -INFINITY, r5 = -INFINITY, r6 = -INFINITY, r7 = -INFINITY;
        if (lane < NWARPS) {
            r0 = s_warp8[lane][0]; r1 = s_warp8[lane][1];
            r2 = s_warp8[lane][2]; r3 = s_warp8[lane][3];
            r4 = s_warp8[lane][4]; r5 = s_warp8[lane][5];
            r6 = s_warp8[lane][6]; r7 = s_warp8[lane][7];
        }
        float myTop = 1.f;   // lane r ends up holding r-th largest (log(1)=0 safe default)
        #pragma unroll
        for (int r = 0; r < 8; ++r) {
            float head = r0;
            float m = warpMaxAll(head);
            unsigned win = __ballot_sync(0xffffffffu, head == m);
            if (lane == __ffs(win) - 1) {
                r0 = r1; r1 = r2; r2 = r3; r3 = r4;
                r4 = r5; r5 = r6; r6 = r7; r7 = -INFINITY;
            }
            if (lane == r) myTop = m;
        }

        const int   tgt  = p_tgt;
        const float dist = p_dist;
        const float lkey = logf(p_key);
        const float lsel = logf(p_sel);

        // duplicate-label group mask (counts + last-wins scatter)
        unsigned mm = __match_any_sync(0xffffffffu, tgt);
        int first = __ffs(mm) - 1;
        int last  = 31 - __clz(mm);

        // distinct-label prefix counts (label 0 never counted — reference quirk)
        int cnt = (tgt != 0 && first == lane) ? 1 : 0;
        #pragma unroll
        for (int o = 1; o < 32; o <<= 1) {
            int n = __shfl_up_sync(0xffffffffu, cnt, o);
            if (lane >= o) cnt += n;
        }
        const float cntf = (float)cnt;

        // noise_logit: 2 -> 4 tanh -> 1
        float noise = b1b[0];
        #pragma unroll
        for (int a = 0; a < 4; ++a) {
            float h = tanhf(b1a[a] + W1a[a * 2] * lkey + W1a[a * 2 + 1] * lsel);
            noise += W1b[a] * h;
        }

        // sim_lambda = W_func . [log(top8), log_key, log_sel] + b_func
        float part = W_func[8 + lane] * lkey + W_func[40 + lane] * lsel;
        if (lane < 8) part += W_func[lane] * logf(myTop);
        const float sim = warpSumAll(part) + b_func[0];

        // lambda_logit = W2b . tanh(W2a . [dists, counts] + b2a) + b2b
        s_dist[lane] = dist; s_cnt[lane] = cntf;
        __syncwarp();
        float h = b2a[lane];
        const float* w = W2a + lane * 64;
        #pragma unroll 8
        for (int k = 0; k < KNN_K; ++k)
            h += w[k] * s_dist[k] + w[KNN_K + k] * s_cnt[k];
        h = tanhf(h);
        const float l0 = warpSumAll(W2b[lane] * h) + b2b[0];
        const float l1 = warpSumAll(W2b[32 + lane] * h) + b2b[1];

        const float lam   = 1.f / (1.f + expf(sim - l0));  // softmax([l0,sim])[0]
        const float tempe = 1.f / (1.f + expf(-l1));

        // probs = softmax(-dist*tempe + noise) over K
        const float logit = -dist * tempe + noise;
        const float mx = warpMaxAll(logit);
        const float e  = expf(logit - mx);
        const float sm = warpSumAll(e);

        // scatter: duplicate tgt within row -> LAST occurrence wins
        if (lane == last)
            out[rbase + (size_t)tgt] = e / sm;
        if (lane == 0 && write_lambda)
            out[(size_t)n_rows * (size_t)V + row] = lam;
    }
}

extern "C" void kernel_launch(void* const* d_in, const int* in_sizes, int n_in,
                              void* d_out, int out_size)
{
    const int* tgt_index        = (const int*)  d_in[0];
    const float* knn_dists      = (const float*)d_in[1];
    const float* knn_key        = (const float*)d_in[2];
    const float* network_probs  = (const float*)d_in[3];
    const float* net_sel        = (const float*)d_in[4];
    const float* W_func = (const float*)d_in[5];
    const float* b_func = (const float*)d_in[6];
    const float* W1a    = (const float*)d_in[7];
    const float* b1a    = (const float*)d_in[8];
    const float* W1b    = (const float*)d_in[9];
    const float* b1b    = (const float*)d_in[10];
    const float* W2a    = (const float*)d_in[11];
    const float* b2a    = (const float*)d_in[12];
    const float* W2b    = (const float*)d_in[13];
    const float* b2b    = (const float*)d_in[14];

    const int n_rows = in_sizes[1] / KNN_K;            // B*S = 2048
    const int V      = in_sizes[3] / n_rows;           // 32000
    const int write_lambda =
        ((long long)out_size >= (long long)n_rows * V + n_rows) ? 1 : 0;

    robust_combiner_kernel<<<n_rows, NTHREADS>>>(
        tgt_index, knn_dists, knn_key, network_probs, net_sel,
        W_func, b_func, W1a, b1a, W1b, b1b, W2a, b2a, W2b, b2b,
        (float*)d_out, V, n_rows, write_lambda);
}